// round 15
// baseline (speedup 1.0000x reference)
#include <cuda_runtime.h>

#define BDIM 128
#define HDIM 32
#define SDIM 64
#define DDIM 128
#define STARTLEN 32
#define NT 512
#define G 16
#define BSTR (HDIM * SDIM * DDIM)     // one-batch stride in k/v arrays (floats)

// SMEM (floats): CW [128 d][384 e] = 49152 (192KB, weights; reused as epilogue scratch),
// XS cur[16][128] = 2048, QS q[16][128] = 2048, AT att[16][64] = 1024
#define CW 0
#define XS 49152
#define QS 51200
#define AT 53248
#define SMEM_FLOATS 54272             // 217088 B -> 1 CTA/SM

// Fused weights per head, layout [h][d(128)][384] where col = m*128 + e  (m: 0=q,1=k,2=v)
__device__ float g_comb[HDIM * DDIM * 384];

// ---------------- fuse kernel: C = Wo @ Wm -> g_comb[h][a][m*128+e] ----------------
__global__ void __launch_bounds__(256)
fuse_weights_kernel(const float* __restrict__ wq, const float* __restrict__ wk,
                    const float* __restrict__ wv, const float* __restrict__ wo)
{
    __shared__ float Ws[DDIM * DDIM];
    __shared__ float Wop[32 * DDIM];
    const int h    = blockIdx.x / 12;
    const int rem  = blockIdx.x % 12;
    const int m    = rem >> 2;
    const int d0   = (rem & 3) << 5;
    const int t    = threadIdx.x;

    const float* Wm = ((m == 0) ? wq : ((m == 1) ? wk : wv)) + (size_t)h * DDIM * DDIM;
    const float* Wo = wo + (size_t)h * DDIM * DDIM;

    for (int i = t; i < DDIM * DDIM / 4; i += 256)
        ((float4*)Ws)[i] = ((const float4*)Wm)[i];
    for (int i = t; i < 32 * DDIM / 4; i += 256)
        ((float4*)Wop)[i] = ((const float4*)(Wo + d0 * DDIM))[i];
    __syncthreads();

    const int c = t & 15;
    const int r = t >> 4;
    float acc[2][8];
    #pragma unroll
    for (int i = 0; i < 2; ++i)
        #pragma unroll
        for (int j = 0; j < 8; ++j) acc[i][j] = 0.f;

    #pragma unroll 4
    for (int e = 0; e < DDIM; ++e) {
        float4 wm0 = *(const float4*)&Ws[e * DDIM + c * 8];
        float4 wm1 = *(const float4*)&Ws[e * DDIM + c * 8 + 4];
        #pragma unroll
        for (int i = 0; i < 2; ++i) {
            float wo_v = Wop[(r * 2 + i) * DDIM + e];
            acc[i][0] += wo_v * wm0.x; acc[i][1] += wo_v * wm0.y;
            acc[i][2] += wo_v * wm0.z; acc[i][3] += wo_v * wm0.w;
            acc[i][4] += wo_v * wm1.x; acc[i][5] += wo_v * wm1.y;
            acc[i][6] += wo_v * wm1.z; acc[i][7] += wo_v * wm1.w;
        }
    }

    // dst row a = d0 + r*2 + i (input dim), cols at m*128 + c*8
    float* dst = g_comb + (size_t)h * (DDIM * 384) + m * DDIM;
    #pragma unroll
    for (int i = 0; i < 2; ++i) {
        size_t ro = (size_t)(d0 + r * 2 + i) * 384;
        *(float4*)&dst[ro + c * 8]     = make_float4(acc[i][0], acc[i][1], acc[i][2], acc[i][3]);
        *(float4*)&dst[ro + c * 8 + 4] = make_float4(acc[i][4], acc[i][5], acc[i][6], acc[i][7]);
    }
}

// ---------------- decode kernel: weights resident in smem ----------------
__global__ void __launch_bounds__(NT, 1)
attn_decode_kernel(const float* __restrict__ x_in,
                   const float* __restrict__ k_in,
                   const float* __restrict__ v_in,
                   const float* __restrict__ wq,
                   const float* __restrict__ wk,
                   const float* __restrict__ wv,
                   const float* __restrict__ wo,
                   float* k_out, float* v_out, float* __restrict__ x_out)
{
    extern __shared__ float sm[];

    const int t = threadIdx.x;
    const int w = t >> 5;
    const int l = t & 31;
    const int h  = blockIdx.x >> 3;          // 8 batch-groups per head
    const int b0 = (blockIdx.x & 7) << 4;    // 16 batches per CTA

    float* kg = k_out + (size_t)(b0 * HDIM + h) * (SDIM * DDIM);
    float* vg = v_out + (size_t)(b0 * HDIM + h) * (SDIM * DDIM);

    // ---- prologue ----
    {   // K,V write-through caches (16 batches)
        const float4* kin = (const float4*)(k_in + (size_t)(b0 * HDIM + h) * (SDIM * DDIM));
        const float4* vin = (const float4*)(v_in + (size_t)(b0 * HDIM + h) * (SDIM * DDIM));
        for (int i = t; i < G * 2048; i += NT) {
            int b = i >> 11, j = i & 2047;
            size_t off = (size_t)b * (BSTR / 4) + j;
            ((float4*)kg)[off] = kin[off];
            ((float4*)vg)[off] = vin[off];
        }
        // x -> XS [b][d]
        for (int i = t; i < G * DDIM; i += NT) {
            int b = i >> 7, d = i & 127;
            sm[XS + i] = x_in[(size_t)((b0 + b) * HDIM + h) * DDIM + d];
        }
        // original weights -> CW [d][m*128+e] (used for first step only)
        const float* Wm[3] = { wq + (size_t)h * DDIM * DDIM,
                               wk + (size_t)h * DDIM * DDIM,
                               wv + (size_t)h * DDIM * DDIM };
        #pragma unroll
        for (int m = 0; m < 3; ++m) {
            const float4* src = (const float4*)Wm[m];
            for (int i = t; i < 4096; i += NT) {
                int d = i >> 5, e4 = i & 31;
                *(float4*)&sm[CW + d * 384 + m * 128 + 4 * e4] = src[i];
            }
        }
    }
    __syncthreads();

    // P1 task (warps 0-11): e-block eb (0=q,1=k,2=v), batch-quad bq
    const int eb = (w < 12) ? (w % 3) : 0;
    const int bq = (w < 12) ? (w / 3) : 0;

    for (int gen = STARTLEN; gen < SDIM; ++gen) {
        // ===== Phase A: projections from smem weights, full dots (no partials) =====
        if (w < 12) {
            float4 a0 = {0,0,0,0}, a1 = {0,0,0,0}, a2 = {0,0,0,0}, a3 = {0,0,0,0};
            const float4* Wf = (const float4*)&sm[CW] + eb * 32 + l;
            const float* xb = sm + XS + (bq << 2) * 128;
            #pragma unroll 4
            for (int d = 0; d < 128; ++d) {
                float4 w4 = Wf[d * 96];
                float x0 = xb[d];
                float x1 = xb[128 + d];
                float x2 = xb[256 + d];
                float x3 = xb[384 + d];
                a0.x += x0 * w4.x; a0.y += x0 * w4.y; a0.z += x0 * w4.z; a0.w += x0 * w4.w;
                a1.x += x1 * w4.x; a1.y += x1 * w4.y; a1.z += x1 * w4.z; a1.w += x1 * w4.w;
                a2.x += x2 * w4.x; a2.y += x2 * w4.y; a2.z += x2 * w4.z; a2.w += x2 * w4.w;
                a3.x += x3 * w4.x; a3.y += x3 * w4.y; a3.z += x3 * w4.z; a3.w += x3 * w4.w;
            }
            if (eb == 0) {          // q (scaled) -> smem
                *(float4*)&sm[QS + ((bq << 2) + 0) * 128 + 4 * l] = make_float4(a0.x*0.125f, a0.y*0.125f, a0.z*0.125f, a0.w*0.125f);
                *(float4*)&sm[QS + ((bq << 2) + 1) * 128 + 4 * l] = make_float4(a1.x*0.125f, a1.y*0.125f, a1.z*0.125f, a1.w*0.125f);
                *(float4*)&sm[QS + ((bq << 2) + 2) * 128 + 4 * l] = make_float4(a2.x*0.125f, a2.y*0.125f, a2.z*0.125f, a2.w*0.125f);
                *(float4*)&sm[QS + ((bq << 2) + 3) * 128 + 4 * l] = make_float4(a3.x*0.125f, a3.y*0.125f, a3.z*0.125f, a3.w*0.125f);
            } else if (eb == 1) {   // k[gen] -> global cache
                *(float4*)&kg[(size_t)((bq << 2) + 0) * BSTR + gen * DDIM + 4 * l] = a0;
                *(float4*)&kg[(size_t)((bq << 2) + 1) * BSTR + gen * DDIM + 4 * l] = a1;
                *(float4*)&kg[(size_t)((bq << 2) + 2) * BSTR + gen * DDIM + 4 * l] = a2;
                *(float4*)&kg[(size_t)((bq << 2) + 3) * BSTR + gen * DDIM + 4 * l] = a3;
            } else {                // v[gen] -> global cache
                *(float4*)&vg[(size_t)((bq << 2) + 0) * BSTR + gen * DDIM + 4 * l] = a0;
                *(float4*)&vg[(size_t)((bq << 2) + 1) * BSTR + gen * DDIM + 4 * l] = a1;
                *(float4*)&vg[(size_t)((bq << 2) + 2) * BSTR + gen * DDIM + 4 * l] = a2;
                *(float4*)&vg[(size_t)((bq << 2) + 3) * BSTR + gen * DDIM + 4 * l] = a3;
            }
        }
        __syncthreads();

        // ===== Phase B: warp-per-batch attention (scores + softmax + AV) =====
        {
            const int b = w;
            float4 q4 = *(const float4*)&sm[QS + b * 128 + 4 * l];
            const float4* kb4 = (const float4*)(kg + (size_t)b * BSTR) + l;
            #pragma unroll 8
            for (int s = 0; s < SDIM; ++s) {
                float4 k4 = kb4[s * 32];
                float p = k4.x * q4.x + k4.y * q4.y + k4.z * q4.z + k4.w * q4.w;
                #pragma unroll
                for (int o = 16; o > 0; o >>= 1) p += __shfl_xor_sync(0xFFFFFFFFu, p, o);
                if (l == 0) sm[AT + b * SDIM + s] = p;
            }
            __syncwarp();
            float s0 = sm[AT + b * SDIM + l];
            float s1 = sm[AT + b * SDIM + 32 + l];
            float mx = fmaxf(s0, s1);
            #pragma unroll
            for (int o = 16; o > 0; o >>= 1) mx = fmaxf(mx, __shfl_xor_sync(0xFFFFFFFFu, mx, o));
            float e0 = __expf(s0 - mx);
            float e1 = __expf(s1 - mx);
            float su = e0 + e1;
            #pragma unroll
            for (int o = 16; o > 0; o >>= 1) su += __shfl_xor_sync(0xFFFFFFFFu, su, o);
            float inv = 1.0f / su;
            float p0 = e0 * inv, p1 = e1 * inv;

            const float4* vb4 = (const float4*)(vg + (size_t)b * BSTR) + l;
            float4 acc = {0,0,0,0};
            #pragma unroll 8
            for (int s = 0; s < 32; ++s) {
                float a = __shfl_sync(0xFFFFFFFFu, p0, s);
                float4 v4 = vb4[s * 32];
                acc.x += a * v4.x; acc.y += a * v4.y; acc.z += a * v4.z; acc.w += a * v4.w;
            }
            #pragma unroll 8
            for (int s = 0; s < 32; ++s) {
                float a = __shfl_sync(0xFFFFFFFFu, p1, s);
                float4 v4 = vb4[(32 + s) * 32];
                acc.x += a * v4.x; acc.y += a * v4.y; acc.z += a * v4.z; acc.w += a * v4.w;
            }
            *(float4*)&sm[XS + b * 128 + 4 * l] = acc;   // next step's input
        }
        __syncthreads();

        // after first step: swap smem weights to the fused matrices (once)
        if (gen == STARTLEN) {
            const float4* src = (const float4*)(g_comb + (size_t)h * (DDIM * 384));
            float4* dst = (float4*)&sm[CW];
            for (int i = t; i < 12288; i += NT) dst[i] = src[i];
            __syncthreads();
        }
    }

    // ---- epilogue: x_out = XS @ Wo; partials staged in CW (weights dead) ----
    const float4* Wo4 = (const float4*)(wo + (size_t)h * DDIM * DDIM);
    {
        const int ebq = w >> 2;     // batch quad
        const int dh  = w & 3;      // d quarter
        float4 a0 = {0,0,0,0}, a1 = {0,0,0,0}, a2 = {0,0,0,0}, a3 = {0,0,0,0};
        const float* xb = sm + XS + (ebq << 2) * 128;
        #pragma unroll 8
        for (int dd = 0; dd < 32; ++dd) {
            int d = dh * 32 + dd;
            float4 w4 = Wo4[d * 32 + l];
            float x0 = xb[d];
            float x1 = xb[128 + d];
            float x2 = xb[256 + d];
            float x3 = xb[384 + d];
            a0.x += x0 * w4.x; a0.y += x0 * w4.y; a0.z += x0 * w4.z; a0.w += x0 * w4.w;
            a1.x += x1 * w4.x; a1.y += x1 * w4.y; a1.z += x1 * w4.z; a1.w += x1 * w4.w;
            a2.x += x2 * w4.x; a2.y += x2 * w4.y; a2.z += x2 * w4.z; a2.w += x2 * w4.w;
            a3.x += x3 * w4.x; a3.y += x3 * w4.y; a3.z += x3 * w4.z; a3.w += x3 * w4.w;
        }
        *(float4*)&sm[CW + (w * 4 + 0) * 128 + 4 * l] = a0;
        *(float4*)&sm[CW + (w * 4 + 1) * 128 + 4 * l] = a1;
        *(float4*)&sm[CW + (w * 4 + 2) * 128 + 4 * l] = a2;
        *(float4*)&sm[CW + (w * 4 + 3) * 128 + 4 * l] = a3;
    }
    __syncthreads();
    for (int i = t; i < G * DDIM; i += NT) {
        int b = i >> 7, e = i & 127;
        int bq2 = b >> 2, j = b & 3;
        float v = 0.f;
        #pragma unroll
        for (int dh = 0; dh < 4; ++dh)
            v += sm[CW + ((bq2 * 4 + dh) * 4 + j) * 128 + e];
        x_out[(size_t)((b0 + b) * HDIM + h) * DDIM + e] = v;
    }
}

extern "C" void kernel_launch(void* const* d_in, const int* in_sizes, int n_in,
                              void* d_out, int out_size)
{
    const float* x  = (const float*)d_in[0];
    const float* k  = (const float*)d_in[1];
    const float* v  = (const float*)d_in[2];
    const float* wq = (const float*)d_in[3];
    const float* wk = (const float*)d_in[4];
    const float* wv = (const float*)d_in[5];
    const float* wo = (const float*)d_in[6];

    float* out   = (float*)d_out;
    float* k_out = out;
    float* v_out = out + (size_t)BDIM * HDIM * SDIM * DDIM;
    float* x_out = out + (size_t)2 * BDIM * HDIM * SDIM * DDIM;

    fuse_weights_kernel<<<HDIM * 12, 256>>>(wq, wk, wv, wo);

    size_t smem = SMEM_FLOATS * sizeof(float);
    cudaFuncSetAttribute(attn_decode_kernel,
                         cudaFuncAttributeMaxDynamicSharedMemorySize, (int)smem);
    attn_decode_kernel<<<(BDIM / G) * HDIM, NT, smem>>>(
        x, k, v, wq, wk, wv, wo, k_out, v_out, x_out);
}

// round 16
// speedup vs baseline: 1.0850x; 1.0850x over previous
#include <cuda_runtime.h>

#define BDIM 128
#define HDIM 32
#define SDIM 64
#define DDIM 128
#define STARTLEN 32
#define NT 384
#define G 4
#define BSTR (HDIM * SDIM * DDIM)

// SMEM (floats): CW [128 d][384 e] = 49152 (weights, resident),
// XS cur[4][128] = 512, QS q[4][128] = 512, AT att[4][64] = 256, RED [48][128] = 6144
#define CW  0
#define XS  49152
#define QS  49664
#define AT  50176
#define RED 50432
#define SMEM_FLOATS 56576            // 226304 B -> 1 CTA/SM

// Fused weights per head, layout [h][d(128)][384], col = m*128 + e  (m: 0=q,1=k,2=v)
__device__ float g_comb[HDIM * DDIM * 384];

// ---------------- fuse kernel: C = Wo @ Wm -> g_comb[h][a][m*128+e] ----------------
__global__ void __launch_bounds__(256)
fuse_weights_kernel(const float* __restrict__ wq, const float* __restrict__ wk,
                    const float* __restrict__ wv, const float* __restrict__ wo)
{
    __shared__ float Ws[DDIM * DDIM];
    __shared__ float Wop[32 * DDIM];
    const int h    = blockIdx.x / 12;
    const int rem  = blockIdx.x % 12;
    const int m    = rem >> 2;
    const int d0   = (rem & 3) << 5;
    const int t    = threadIdx.x;

    const float* Wm = ((m == 0) ? wq : ((m == 1) ? wk : wv)) + (size_t)h * DDIM * DDIM;
    const float* Wo = wo + (size_t)h * DDIM * DDIM;

    for (int i = t; i < DDIM * DDIM / 4; i += 256)
        ((float4*)Ws)[i] = ((const float4*)Wm)[i];
    for (int i = t; i < 32 * DDIM / 4; i += 256)
        ((float4*)Wop)[i] = ((const float4*)(Wo + d0 * DDIM))[i];
    __syncthreads();

    const int c = t & 15;
    const int r = t >> 4;
    float acc[2][8];
    #pragma unroll
    for (int i = 0; i < 2; ++i)
        #pragma unroll
        for (int j = 0; j < 8; ++j) acc[i][j] = 0.f;

    #pragma unroll 4
    for (int e = 0; e < DDIM; ++e) {
        float4 wm0 = *(const float4*)&Ws[e * DDIM + c * 8];
        float4 wm1 = *(const float4*)&Ws[e * DDIM + c * 8 + 4];
        #pragma unroll
        for (int i = 0; i < 2; ++i) {
            float wo_v = Wop[(r * 2 + i) * DDIM + e];
            acc[i][0] += wo_v * wm0.x; acc[i][1] += wo_v * wm0.y;
            acc[i][2] += wo_v * wm0.z; acc[i][3] += wo_v * wm0.w;
            acc[i][4] += wo_v * wm1.x; acc[i][5] += wo_v * wm1.y;
            acc[i][6] += wo_v * wm1.z; acc[i][7] += wo_v * wm1.w;
        }
    }

    float* dst = g_comb + (size_t)h * (DDIM * 384) + m * DDIM;
    #pragma unroll
    for (int i = 0; i < 2; ++i) {
        size_t ro = (size_t)(d0 + r * 2 + i) * 384;
        *(float4*)&dst[ro + c * 8]     = make_float4(acc[i][0], acc[i][1], acc[i][2], acc[i][3]);
        *(float4*)&dst[ro + c * 8 + 4] = make_float4(acc[i][4], acc[i][5], acc[i][6], acc[i][7]);
    }
}

// ---------------- decode kernel: weights resident in smem, G=4 ----------------
__global__ void __launch_bounds__(NT, 1)
attn_decode_kernel(const float* __restrict__ x_in,
                   const float* __restrict__ k_in,
                   const float* __restrict__ v_in,
                   const float* __restrict__ wq,
                   const float* __restrict__ wk,
                   const float* __restrict__ wv,
                   const float* __restrict__ wo,
                   float* k_out, float* v_out, float* __restrict__ x_out)
{
    extern __shared__ float sm[];

    const int t = threadIdx.x;
    const int w = t >> 5;
    const int l = t & 31;
    const int h  = blockIdx.x >> 5;          // 32 batch-groups per head
    const int b0 = (blockIdx.x & 31) << 2;   // 4 batches per CTA

    float* kg = k_out + (size_t)(b0 * HDIM + h) * (SDIM * DDIM);
    float* vg = v_out + (size_t)(b0 * HDIM + h) * (SDIM * DDIM);

    // ---- prologue: K,V -> write-through caches; x -> XS; orig weights -> CW ----
    {
        const float4* kin = (const float4*)(k_in + (size_t)(b0 * HDIM + h) * (SDIM * DDIM));
        const float4* vin = (const float4*)(v_in + (size_t)(b0 * HDIM + h) * (SDIM * DDIM));
        for (int i = t; i < G * 2048; i += NT) {
            int b = i >> 11, j = i & 2047;
            size_t off = (size_t)b * (BSTR / 4) + j;
            ((float4*)kg)[off] = kin[off];
            ((float4*)vg)[off] = vin[off];
        }
        for (int i = t; i < G * DDIM; i += NT) {
            int b = i >> 7, d = i & 127;
            sm[XS + i] = x_in[(size_t)((b0 + b) * HDIM + h) * DDIM + d];
        }
        const float* Wm[3] = { wq + (size_t)h * DDIM * DDIM,
                               wk + (size_t)h * DDIM * DDIM,
                               wv + (size_t)h * DDIM * DDIM };
        #pragma unroll
        for (int m = 0; m < 3; ++m) {
            const float4* src = (const float4*)Wm[m];
            for (int i = t; i < 4096; i += NT) {
                int d = i >> 5, e4 = i & 31;
                *(float4*)&sm[CW + d * 384 + m * 128 + 4 * e4] = src[i];
            }
        }
    }
    __syncthreads();

    // P1 task (warps 0-11): e-block eb (0=q,1=k,2=v cols), d-quarter dq
    const int eb = w % 3;
    const int dq = w / 3;

    for (int gen = STARTLEN; gen < SDIM; ++gen) {
        // ===== P1: projections from smem weights; 16 FMA per weight LDS.128 =====
        if (w < 12) {
            const float4* Wf = (const float4*)&sm[CW] + eb * 32 + l;   // + d*96
            float4 a0 = {0,0,0,0}, a1 = {0,0,0,0}, a2 = {0,0,0,0}, a3 = {0,0,0,0};
            const int d0 = dq << 5;
            #pragma unroll 8
            for (int i = 0; i < 32; ++i) {
                int d = d0 + i;
                float4 w4 = Wf[d * 96];
                float x0 = sm[XS + d];
                float x1 = sm[XS + 128 + d];
                float x2 = sm[XS + 256 + d];
                float x3 = sm[XS + 384 + d];
                a0.x += x0 * w4.x; a0.y += x0 * w4.y; a0.z += x0 * w4.z; a0.w += x0 * w4.w;
                a1.x += x1 * w4.x; a1.y += x1 * w4.y; a1.z += x1 * w4.z; a1.w += x1 * w4.w;
                a2.x += x2 * w4.x; a2.y += x2 * w4.y; a2.z += x2 * w4.z; a2.w += x2 * w4.w;
                a3.x += x3 * w4.x; a3.y += x3 * w4.y; a3.z += x3 * w4.z; a3.w += x3 * w4.w;
            }
            const int base = (eb * 4 + dq) * 4;
            *(float4*)&sm[RED + (base + 0) * 128 + 4 * l] = a0;
            *(float4*)&sm[RED + (base + 1) * 128 + 4 * l] = a1;
            *(float4*)&sm[RED + (base + 2) * 128 + 4 * l] = a2;
            *(float4*)&sm[RED + (base + 3) * 128 + 4 * l] = a3;
        }
        __syncthreads();

        // ===== reduce: 4 d-quarter partials -> q (smem), k[gen] & v[gen] (global) =====
        #pragma unroll
        for (int ii = 0; ii < 4; ++ii) {
            int i = ii * NT + t;                 // 0..1535
            int m = i >> 9, b = (i >> 7) & 3, e = i & 127;
            float v = sm[RED + ((m * 4 + 0) * 4 + b) * 128 + e]
                    + sm[RED + ((m * 4 + 1) * 4 + b) * 128 + e]
                    + sm[RED + ((m * 4 + 2) * 4 + b) * 128 + e]
                    + sm[RED + ((m * 4 + 3) * 4 + b) * 128 + e];
            if (m == 0)      sm[QS + b * 128 + e] = v * 0.125f;
            else if (m == 1) kg[(size_t)b * BSTR + gen * DDIM + e] = v;
            else             vg[(size_t)b * BSTR + gen * DDIM + e] = v;
        }
        __syncthreads();

        // ===== P2 (w<8): QK scores from global K, warp = (batch, s-half) =====
        if (w < 8) {
            const int b = w >> 1, sh = w & 1;
            float4 q4 = *(const float4*)&sm[QS + b * 128 + 4 * l];
            const float4* kb4 = (const float4*)(kg + (size_t)b * BSTR) + l;
            #pragma unroll 8
            for (int r = 0; r < 32; ++r) {
                int s = (sh << 5) + r;
                float4 k4 = kb4[s * 32];
                float p = k4.x * q4.x + k4.y * q4.y + k4.z * q4.z + k4.w * q4.w;
                #pragma unroll
                for (int o = 16; o > 0; o >>= 1) p += __shfl_xor_sync(0xFFFFFFFFu, p, o);
                if (l == 0) sm[AT + b * SDIM + s] = p;
            }
        }
        __syncthreads();

        // ===== P4 (w<4): warp-per-batch register softmax + float4 AV -> XS =====
        if (w < 4) {
            const int b = w;
            float s0 = sm[AT + b * SDIM + l];
            float s1 = sm[AT + b * SDIM + 32 + l];
            float mx = fmaxf(s0, s1);
            #pragma unroll
            for (int o = 16; o > 0; o >>= 1) mx = fmaxf(mx, __shfl_xor_sync(0xFFFFFFFFu, mx, o));
            float e0 = __expf(s0 - mx);
            float e1 = __expf(s1 - mx);
            float su = e0 + e1;
            #pragma unroll
            for (int o = 16; o > 0; o >>= 1) su += __shfl_xor_sync(0xFFFFFFFFu, su, o);
            float inv = 1.0f / su;
            float p0 = e0 * inv, p1 = e1 * inv;

            const float4* vb4 = (const float4*)(vg + (size_t)b * BSTR) + l;
            float4 acc = {0,0,0,0};
            #pragma unroll 8
            for (int s = 0; s < 32; ++s) {
                float a = __shfl_sync(0xFFFFFFFFu, p0, s);
                float4 v4 = vb4[s * 32];
                acc.x += a * v4.x; acc.y += a * v4.y; acc.z += a * v4.z; acc.w += a * v4.w;
            }
            #pragma unroll 8
            for (int s = 0; s < 32; ++s) {
                float a = __shfl_sync(0xFFFFFFFFu, p1, s);
                float4 v4 = vb4[(32 + s) * 32];
                acc.x += a * v4.x; acc.y += a * v4.y; acc.z += a * v4.z; acc.w += a * v4.w;
            }
            *(float4*)&sm[XS + b * 128 + 4 * l] = acc;   // next step's input
        }
        __syncthreads();

        // after first step: swap smem weights to the fused matrices (once)
        if (gen == STARTLEN) {
            const float4* src = (const float4*)(g_comb + (size_t)h * (DDIM * 384));
            float4* dst = (float4*)&sm[CW];
            for (int i = t; i < 12288; i += NT) dst[i] = src[i];
            __syncthreads();
        }
    }

    // ---- epilogue: x_out = XS @ Wo (8 warps x 16 d-rows, partials in RED) ----
    const float4* Wo4 = (const float4*)(wo + (size_t)h * DDIM * DDIM);
    if (w < 8) {
        float4 a0 = {0,0,0,0}, a1 = {0,0,0,0}, a2 = {0,0,0,0}, a3 = {0,0,0,0};
        const int d0 = w << 4;
        #pragma unroll 8
        for (int dd = 0; dd < 16; ++dd) {
            int d = d0 + dd;
            float4 w4 = Wo4[d * 32 + l];
            float x0 = sm[XS + d];
            float x1 = sm[XS + 128 + d];
            float x2 = sm[XS + 256 + d];
            float x3 = sm[XS + 384 + d];
            a0.x += x0 * w4.x; a0.y += x0 * w4.y; a0.z += x0 * w4.z; a0.w += x0 * w4.w;
            a1.x += x1 * w4.x; a1.y += x1 * w4.y; a1.z += x1 * w4.z; a1.w += x1 * w4.w;
            a2.x += x2 * w4.x; a2.y += x2 * w4.y; a2.z += x2 * w4.z; a2.w += x2 * w4.w;
            a3.x += x3 * w4.x; a3.y += x3 * w4.y; a3.z += x3 * w4.z; a3.w += x3 * w4.w;
        }
        *(float4*)&sm[RED + (w * 4 + 0) * 128 + 4 * l] = a0;
        *(float4*)&sm[RED + (w * 4 + 1) * 128 + 4 * l] = a1;
        *(float4*)&sm[RED + (w * 4 + 2) * 128 + 4 * l] = a2;
        *(float4*)&sm[RED + (w * 4 + 3) * 128 + 4 * l] = a3;
    }
    __syncthreads();
    for (int i = t; i < G * DDIM; i += NT) {
        int b = i >> 7, e = i & 127;
        float v = 0.f;
        #pragma unroll
        for (int ww = 0; ww < 8; ++ww)
            v += sm[RED + (ww * 4 + b) * 128 + e];
        x_out[(size_t)((b0 + b) * HDIM + h) * DDIM + e] = v;
    }
}

extern "C" void kernel_launch(void* const* d_in, const int* in_sizes, int n_in,
                              void* d_out, int out_size)
{
    const float* x  = (const float*)d_in[0];
    const float* k  = (const float*)d_in[1];
    const float* v  = (const float*)d_in[2];
    const float* wq = (const float*)d_in[3];
    const float* wk = (const float*)d_in[4];
    const float* wv = (const float*)d_in[5];
    const float* wo = (const float*)d_in[6];

    float* out   = (float*)d_out;
    float* k_out = out;
    float* v_out = out + (size_t)BDIM * HDIM * SDIM * DDIM;
    float* x_out = out + (size_t)2 * BDIM * HDIM * SDIM * DDIM;

    fuse_weights_kernel<<<HDIM * 12, 256>>>(wq, wk, wv, wo);

    size_t smem = SMEM_FLOATS * sizeof(float);
    cudaFuncSetAttribute(attn_decode_kernel,
                         cudaFuncAttributeMaxDynamicSharedMemorySize, (int)smem);
    attn_decode_kernel<<<(BDIM / G) * HDIM, NT, smem>>>(
        x, k, v, wq, wk, wv, wo, k_out, v_out, x_out);
}

// round 17
// speedup vs baseline: 1.6084x; 1.4823x over previous
#include <cuda_runtime.h>
#include <cuda_bf16.h>

#define BDIM 128
#define HDIM 32
#define SDIM 64
#define DDIM 128
#define STARTLEN 32
#define NT 288                        // 9 warps: 3 per projection matrix, clean segments
#define BSTR (HDIM * SDIM * DDIM)

// SMEM (floats): Vs[2][64][128]=16384, cur[2][128]=256, red[18][128]=2304
#define VS   0
#define CUR  16384
#define RED  16640
#define ATT  (RED + 2 * DDIM)
#define SMEM_FLOATS 18944             // 75776 B -> 3 CTAs/SM

// Fused weights per head, bf16: [h][384][128]  (Wo@Wq | Wo@Wk | Wo@Wv)
__device__ __nv_bfloat16 g_comb[HDIM * 3 * DDIM * DDIM];   // 3 MB

// ---------------- fuse kernel: C = Wo @ Wm (fp32 math, bf16 store) ----------------
__global__ void __launch_bounds__(256)
fuse_weights_kernel(const float* __restrict__ wq, const float* __restrict__ wk,
                    const float* __restrict__ wv, const float* __restrict__ wo)
{
    __shared__ float Ws[DDIM * DDIM];
    __shared__ float Wop[32 * DDIM];
    const int h    = blockIdx.x / 12;
    const int rem  = blockIdx.x % 12;
    const int m    = rem >> 2;
    const int d0   = (rem & 3) << 5;
    const int t    = threadIdx.x;

    const float* Wm = ((m == 0) ? wq : ((m == 1) ? wk : wv)) + (size_t)h * DDIM * DDIM;
    const float* Wo = wo + (size_t)h * DDIM * DDIM;

    for (int i = t; i < DDIM * DDIM / 4; i += 256)
        ((float4*)Ws)[i] = ((const float4*)Wm)[i];
    for (int i = t; i < 32 * DDIM / 4; i += 256)
        ((float4*)Wop)[i] = ((const float4*)(Wo + d0 * DDIM))[i];
    __syncthreads();

    const int c = t & 15;
    const int r = t >> 4;
    float acc[2][8];
    #pragma unroll
    for (int i = 0; i < 2; ++i)
        #pragma unroll
        for (int j = 0; j < 8; ++j) acc[i][j] = 0.f;

    #pragma unroll 4
    for (int e = 0; e < DDIM; ++e) {
        float4 wm0 = *(const float4*)&Ws[e * DDIM + c * 8];
        float4 wm1 = *(const float4*)&Ws[e * DDIM + c * 8 + 4];
        #pragma unroll
        for (int i = 0; i < 2; ++i) {
            float wo_v = Wop[(r * 2 + i) * DDIM + e];
            acc[i][0] += wo_v * wm0.x; acc[i][1] += wo_v * wm0.y;
            acc[i][2] += wo_v * wm0.z; acc[i][3] += wo_v * wm0.w;
            acc[i][4] += wo_v * wm1.x; acc[i][5] += wo_v * wm1.y;
            acc[i][6] += wo_v * wm1.z; acc[i][7] += wo_v * wm1.w;
        }
    }

    __nv_bfloat16* dst = g_comb + ((size_t)h * 384 + m * DDIM + d0) * DDIM;
    #pragma unroll
    for (int i = 0; i < 2; ++i) {
        __nv_bfloat162 p0 = __floats2bfloat162_rn(acc[i][0], acc[i][1]);
        __nv_bfloat162 p1 = __floats2bfloat162_rn(acc[i][2], acc[i][3]);
        __nv_bfloat162 p2 = __floats2bfloat162_rn(acc[i][4], acc[i][5]);
        __nv_bfloat162 p3 = __floats2bfloat162_rn(acc[i][6], acc[i][7]);
        uint4 pk;
        pk.x = *(unsigned*)&p0; pk.y = *(unsigned*)&p1;
        pk.z = *(unsigned*)&p2; pk.w = *(unsigned*)&p3;
        *(uint4*)&dst[(r * 2 + i) * DDIM + c * 8] = pk;
    }
}

// ---------------- decode kernel ----------------
__global__ void __launch_bounds__(NT, 3)
attn_decode_kernel(const float* __restrict__ x_in,
                   const float* __restrict__ k_in,
                   const float* __restrict__ v_in,
                   const float* __restrict__ wq,
                   const float* __restrict__ wk,
                   const float* __restrict__ wv,
                   const float* __restrict__ wo,
                   float* k_out, float* v_out, float* __restrict__ x_out)
{
    extern __shared__ float sm[];

    const int t = threadIdx.x;
    const int w = t >> 5;
    const int l = t & 31;
    const int h  = blockIdx.x >> 6;
    const int b0 = (blockIdx.x & 63) << 1;

    float* kg = k_out + (size_t)(b0 * HDIM + h) * (SDIM * DDIM);
    float* vg = v_out + (size_t)(b0 * HDIM + h) * (SDIM * DDIM);

    // ---- prologue: k_in -> k_out (global cache), v_in -> smem + v_out, x -> cur ----
    for (int b = 0; b < 2; ++b) {
        const float4* kin = (const float4*)(k_in + (size_t)((b0 + b) * HDIM + h) * (SDIM * DDIM));
        const float4* vin = (const float4*)(v_in + (size_t)((b0 + b) * HDIM + h) * (SDIM * DDIM));
        float4* kd = (float4*)(kg + (size_t)b * BSTR);
        float4* vd = (float4*)(vg + (size_t)b * BSTR);
        for (int i = t; i < SDIM * DDIM / 4; i += NT) {
            kd[i] = kin[i];
            float4 vv = vin[i];
            *(float4*)&sm[VS + b * 8192 + 4 * i] = vv;
            vd[i] = vv;
        }
        const float* xin = x_in + (size_t)((b0 + b) * HDIM + h) * DDIM;
        for (int d = t; d < DDIM; d += NT) sm[CUR + b * DDIM + d] = xin[d];
    }
    __syncthreads();

    // P1 clean split: matrix pm = w/3, segment ps = w%3; segments 44/44/40, 4-aligned
    const int pm  = w / 3;
    const int ps  = w - pm * 3;
    const int pd0 = ps * 44;
    const int pnR = (ps == 2) ? 40 : 44;

    const float* origM[3] = { wq + (size_t)h * DDIM * DDIM,
                              wk + (size_t)h * DDIM * DDIM,
                              wv + (size_t)h * DDIM * DDIM };

    const float4* orig4 = (const float4*)(origM[pm] + (size_t)pd0 * DDIM);
    // bf16 fused rows: lane l covers e = 4l..4l+3 -> one uint2 (4 bf16), row stride 32 uint2
    const uint2* fusedB = (const uint2*)(g_comb + ((size_t)h * 384 + pm * DDIM + pd0) * DDIM) + l;

    const int p2b = w >> 2, p2s0 = (w & 3) << 4;     // P2 (w<8): (batch, s-quarter)
    const int p4b = t >> 7, p4d = t & 127;           // P4/reduce (t<256): (batch, d)

    for (int gen = STARTLEN; gen < SDIM; ++gen) {
        const bool first = (gen == STARTLEN);

        // ===== P1: projections (fp32 originals first step, bf16 fused after) =====
        {
            float4 a0 = {0,0,0,0}, a1 = {0,0,0,0};
            if (first) {
                #pragma unroll 8
                for (int i = 0; i < pnR; ++i) {
                    float4 wv4 = orig4[i * 32 + l];
                    float x0 = sm[CUR + pd0 + i];
                    float x1 = sm[CUR + DDIM + pd0 + i];
                    a0.x += x0 * wv4.x; a0.y += x0 * wv4.y; a0.z += x0 * wv4.z; a0.w += x0 * wv4.w;
                    a1.x += x1 * wv4.x; a1.y += x1 * wv4.y; a1.z += x1 * wv4.z; a1.w += x1 * wv4.w;
                }
            } else {
                #pragma unroll 8
                for (int i = 0; i < pnR; ++i) {
                    uint2 wb = fusedB[i * 32];
                    float2 f01 = __bfloat1622float2(*(const __nv_bfloat162*)&wb.x);
                    float2 f23 = __bfloat1622float2(*(const __nv_bfloat162*)&wb.y);
                    float x0 = sm[CUR + pd0 + i];
                    float x1 = sm[CUR + DDIM + pd0 + i];
                    a0.x += x0 * f01.x; a0.y += x0 * f01.y; a0.z += x0 * f23.x; a0.w += x0 * f23.y;
                    a1.x += x1 * f01.x; a1.y += x1 * f01.y; a1.z += x1 * f23.x; a1.w += x1 * f23.y;
                }
            }
            *(float4*)&sm[RED + ((w << 1) + 0) * DDIM + (l << 2)] = a0;
            *(float4*)&sm[RED + ((w << 1) + 1) * DDIM + (l << 2)] = a1;
        }
        __syncthreads();

        // ===== reduce (t<256): q -> RED rows 0-1 (scaled); k[gen] -> kg; v[gen] -> Vs + vg =====
        if (t < 256) {
            const int b = p4b, e = p4d;
            float qv = sm[RED + (0 + b) * DDIM + e] + sm[RED + (2 + b) * DDIM + e]
                     + sm[RED + (4 + b) * DDIM + e];
            float kv = sm[RED + (6 + b) * DDIM + e] + sm[RED + (8 + b) * DDIM + e]
                     + sm[RED + (10 + b) * DDIM + e];
            float vv = sm[RED + (12 + b) * DDIM + e] + sm[RED + (14 + b) * DDIM + e]
                     + sm[RED + (16 + b) * DDIM + e];
            sm[RED + b * DDIM + e] = qv * 0.125f;
            kg[(size_t)b * BSTR + gen * DDIM + e] = kv;
            sm[VS + (b * SDIM + gen) * DDIM + e] = vv;
            vg[(size_t)b * BSTR + gen * DDIM + e] = vv;
        }
        __syncthreads();

        // ===== P2 (w<8): QK scores from global K (full-unroll MLP) -> att rows 2-3 =====
        if (w < 8) {
            float4 q4 = *(const float4*)&sm[RED + p2b * DDIM + (l << 2)];
            const float4* kb4 = (const float4*)(kg + (size_t)p2b * BSTR) + l;
            #pragma unroll 16
            for (int r = 0; r < 16; ++r) {
                int s = p2s0 + r;
                float4 k4 = kb4[s * 32];
                float p = k4.x * q4.x + k4.y * q4.y + k4.z * q4.z + k4.w * q4.w;
                #pragma unroll
                for (int o = 16; o > 0; o >>= 1) p += __shfl_xor_sync(0xFFFFFFFFu, p, o);
                if (l == 0) sm[ATT + p2b * SDIM + s] = p;
            }
        }
        __syncthreads();

        // ===== P4 (t<256): per-warp register softmax + AV from smem V -> cur =====
        if (t < 256) {
            float s0 = sm[ATT + p4b * SDIM + l];
            float s1 = sm[ATT + p4b * SDIM + 32 + l];
            float mx = fmaxf(s0, s1);
            #pragma unroll
            for (int o = 16; o > 0; o >>= 1) mx = fmaxf(mx, __shfl_xor_sync(0xFFFFFFFFu, mx, o));
            float e0 = __expf(s0 - mx);
            float e1 = __expf(s1 - mx);
            float su = e0 + e1;
            #pragma unroll
            for (int o = 16; o > 0; o >>= 1) su += __shfl_xor_sync(0xFFFFFFFFu, su, o);
            float inv = 1.0f / su;
            float p0 = e0 * inv, p1 = e1 * inv;

            const float* vb = sm + VS + p4b * (SDIM * DDIM) + p4d;
            float acc = 0.f;
            #pragma unroll 8
            for (int s = 0; s < 32; ++s) {
                float a = __shfl_sync(0xFFFFFFFFu, p0, s);
                acc += a * vb[s * DDIM];
            }
            #pragma unroll 8
            for (int s = 0; s < 32; ++s) {
                float a = __shfl_sync(0xFFFFFFFFu, p1, s);
                acc += a * vb[(32 + s) * DDIM];
            }
            sm[CUR + p4b * DDIM + p4d] = acc;
        }
        __syncthreads();
    }

    // ---- epilogue: x_out = cur @ Wo (fp32 originals) ----
    const float4* Wo4 = (const float4*)(wo + (size_t)h * DDIM * DDIM);
    if (w < 8) {
        float4 a0 = {0,0,0,0}, a1 = {0,0,0,0};
        const int d0 = w << 4;
        #pragma unroll 8
        for (int dd = 0; dd < 16; ++dd) {
            int d = d0 + dd;
            float4 wv4 = Wo4[d * 32 + l];
            float x0 = sm[CUR + d];
            float x1 = sm[CUR + DDIM + d];
            a0.x += x0 * wv4.x; a0.y += x0 * wv4.y; a0.z += x0 * wv4.z; a0.w += x0 * wv4.w;
            a1.x += x1 * wv4.x; a1.y += x1 * wv4.y; a1.z += x1 * wv4.z; a1.w += x1 * wv4.w;
        }
        *(float4*)&sm[RED + ((w << 1) + 0) * DDIM + (l << 2)] = a0;
        *(float4*)&sm[RED + ((w << 1) + 1) * DDIM + (l << 2)] = a1;
    }
    __syncthreads();
    if (t < 256) {
        const int b = p4b, e = p4d;
        float v = 0.f;
        #pragma unroll
        for (int ww = 0; ww < 8; ++ww)
            v += sm[RED + ((ww << 1) + b) * DDIM + e];
        x_out[(size_t)((b0 + b) * HDIM + h) * DDIM + e] = v;
    }
}

extern "C" void kernel_launch(void* const* d_in, const int* in_sizes, int n_in,
                              void* d_out, int out_size)
{
    const float* x  = (const float*)d_in[0];
    const float* k  = (const float*)d_in[1];
    const float* v  = (const float*)d_in[2];
    const float* wq = (const float*)d_in[3];
    const float* wk = (const float*)d_in[4];
    const float* wv = (const float*)d_in[5];
    const float* wo = (const float*)d_in[6];

    float* out   = (float*)d_out;
    float* k_out = out;
    float* v_out = out + (size_t)BDIM * HDIM * SDIM * DDIM;
    float* x_out = out + (size_t)2 * BDIM * HDIM * SDIM * DDIM;

    fuse_weights_kernel<<<HDIM * 12, 256>>>(wq, wk, wv, wo);

    size_t smem = SMEM_FLOATS * sizeof(float);
    cudaFuncSetAttribute(attn_decode_kernel,
                         cudaFuncAttributeMaxDynamicSharedMemorySize, (int)smem);
    attn_decode_kernel<<<BDIM * HDIM / 2, NT, smem>>>(
        x, k, v, wq, wk, wv, wo, k_out, v_out, x_out);
}